// round 2
// baseline (speedup 1.0000x reference)
#include <cuda_runtime.h>
#include <cuda_bf16.h>
#include <math.h>

// Problem constants
#define B_ 16
#define T_ 2048
#define C_ 1024
#define H_ 64
#define M_ (B_ * T_)   // 32768 rows for projection GEMM

// Scratch for projected Q, K, V  (8 MB each; static device arrays — no allocs)
__device__ float g_q[(size_t)M_ * H_];
__device__ float g_k[(size_t)M_ * H_];
__device__ float g_v[(size_t)M_ * H_];

// ---------------------------------------------------------------------------
// Projection GEMM:  O[m,h] = sum_c x[m,c] * W[c,h]
// M=32768, K=1024, N=64.  BM=64, BN=64, BK=32.  128 threads, 4x8 microtile.
// gridDim.y = 3 selects (w_q, w_k, w_v) -> (g_q, g_k, g_v).
// ---------------------------------------------------------------------------
__global__ __launch_bounds__(128) void proj_kernel(
    const float* __restrict__ x,
    const float* __restrict__ wq,
    const float* __restrict__ wk,
    const float* __restrict__ wv)
{
    const float* W;
    float* O;
    if (blockIdx.y == 0)      { W = wq; O = g_q; }
    else if (blockIdx.y == 1) { W = wk; O = g_k; }
    else                      { W = wv; O = g_v; }

    __shared__ float xs[64][33];   // [m][k], pad 33 -> conflict-free STS & 2-way LDS
    __shared__ float ws[32][64];   // [k][h]

    const int tid = threadIdx.x;
    const int ty  = tid >> 3;      // 0..15 -> rows ty*4..ty*4+3
    const int tx  = tid & 7;       // 0..7  -> cols tx*8..tx*8+7
    const int m0  = blockIdx.x * 64;

    float acc[4][8];
#pragma unroll
    for (int i = 0; i < 4; i++)
#pragma unroll
        for (int j = 0; j < 8; j++) acc[i][j] = 0.0f;

    for (int k0 = 0; k0 < C_; k0 += 32) {
        // Load x tile 64x32 (coalesced float4 reads; scalar conflict-free STS)
#pragma unroll
        for (int q = 0; q < 4; q++) {
            int i  = tid + 128 * q;        // 0..511 float4 slots
            int r  = i >> 3;               // row 0..63
            int kq = i & 7;                // float4 within row
            float4 v = *(const float4*)(x + (size_t)(m0 + r) * C_ + k0 + kq * 4);
            xs[r][kq * 4 + 0] = v.x;
            xs[r][kq * 4 + 1] = v.y;
            xs[r][kq * 4 + 2] = v.z;
            xs[r][kq * 4 + 3] = v.w;
        }
        // Load w tile 32x64 (direct float4 copy)
#pragma unroll
        for (int q = 0; q < 4; q++) {
            int i  = tid + 128 * q;        // 0..511 float4 slots
            int kr = i >> 4;               // 0..31
            int cq = i & 15;               // float4 within 64-col row
            *(float4*)(&ws[kr][cq * 4]) =
                *(const float4*)(W + (size_t)(k0 + kr) * H_ + cq * 4);
        }
        __syncthreads();

#pragma unroll
        for (int kk = 0; kk < 32; kk++) {
            float a0 = xs[ty * 4 + 0][kk];
            float a1 = xs[ty * 4 + 1][kk];
            float a2 = xs[ty * 4 + 2][kk];
            float a3 = xs[ty * 4 + 3][kk];
            float4 b0 = *(const float4*)(&ws[kk][tx * 8]);
            float4 b1 = *(const float4*)(&ws[kk][tx * 8 + 4]);

            acc[0][0] += a0 * b0.x; acc[0][1] += a0 * b0.y;
            acc[0][2] += a0 * b0.z; acc[0][3] += a0 * b0.w;
            acc[0][4] += a0 * b1.x; acc[0][5] += a0 * b1.y;
            acc[0][6] += a0 * b1.z; acc[0][7] += a0 * b1.w;

            acc[1][0] += a1 * b0.x; acc[1][1] += a1 * b0.y;
            acc[1][2] += a1 * b0.z; acc[1][3] += a1 * b0.w;
            acc[1][4] += a1 * b1.x; acc[1][5] += a1 * b1.y;
            acc[1][6] += a1 * b1.z; acc[1][7] += a1 * b1.w;

            acc[2][0] += a2 * b0.x; acc[2][1] += a2 * b0.y;
            acc[2][2] += a2 * b0.z; acc[2][3] += a2 * b0.w;
            acc[2][4] += a2 * b1.x; acc[2][5] += a2 * b1.y;
            acc[2][6] += a2 * b1.z; acc[2][7] += a2 * b1.w;

            acc[3][0] += a3 * b0.x; acc[3][1] += a3 * b0.y;
            acc[3][2] += a3 * b0.z; acc[3][3] += a3 * b0.w;
            acc[3][4] += a3 * b1.x; acc[3][5] += a3 * b1.y;
            acc[3][6] += a3 * b1.z; acc[3][7] += a3 * b1.w;
        }
        __syncthreads();
    }

#pragma unroll
    for (int i = 0; i < 4; i++) {
        size_t row = (size_t)(m0 + ty * 4 + i);
        float4 o0 = make_float4(acc[i][0], acc[i][1], acc[i][2], acc[i][3]);
        float4 o1 = make_float4(acc[i][4], acc[i][5], acc[i][6], acc[i][7]);
        *(float4*)(O + row * H_ + tx * 8)     = o0;
        *(float4*)(O + row * H_ + tx * 8 + 4) = o1;
    }
}

// ---------------------------------------------------------------------------
// Flash attention (causal, single head):
// one thread = one query row; 128 query rows per block; K/V tiles (64x64 f32)
// staged in smem; online softmax with lazy rescale.
// grid = (T/128, B), block = 128.
// ---------------------------------------------------------------------------
__global__ __launch_bounds__(128) void attn_kernel(float* __restrict__ out)
{
    const int b   = blockIdx.y;
    // Reverse qt so heaviest (most keys) blocks launch first.
    const int qt  = (gridDim.x - 1 - blockIdx.x);
    const int q0  = qt * 128;
    const int tid = threadIdx.x;
    const int qi  = q0 + tid;

    __shared__ float Ks[64 * 64];
    __shared__ float Vs[64 * 64];

    // Load this thread's query row into registers
    float q[64];
    {
        const float4* qp = (const float4*)(g_q + ((size_t)b * T_ + qi) * H_);
#pragma unroll
        for (int c4 = 0; c4 < 16; c4++) {
            float4 v = qp[c4];
            q[c4 * 4 + 0] = v.x; q[c4 * 4 + 1] = v.y;
            q[c4 * 4 + 2] = v.z; q[c4 * 4 + 3] = v.w;
        }
    }

    float acc[64];
#pragma unroll
    for (int c = 0; c < 64; c++) acc[c] = 0.0f;
    float m = -INFINITY;
    float l = 0.0f;

    const int ktiles = (q0 + 128) / 64;   // tiles covering keys [0, q0+128)

    for (int kt = 0; kt < ktiles; kt++) {
        __syncthreads();   // previous tile fully consumed
        const int kbase = kt * 64;
        {
            const float4* Kp = (const float4*)(g_k + ((size_t)b * T_ + kbase) * H_);
            const float4* Vp = (const float4*)(g_v + ((size_t)b * T_ + kbase) * H_);
            float4* Ks4 = (float4*)Ks;
            float4* Vs4 = (float4*)Vs;
#pragma unroll
            for (int q8 = 0; q8 < 8; q8++) {
                int i = tid + 128 * q8;    // 0..1023 float4 slots
                Ks4[i] = Kp[i];
                Vs4[i] = Vp[i];
            }
        }
        __syncthreads();

        // Per-thread causal bound: keys kbase..kbase+jmax valid (jmax<0 => none)
        const int jmax = min(63, qi - kbase);

        for (int j = 0; j <= jmax; j++) {
            const float* kr = &Ks[j * 64];
            float s = 0.0f;
#pragma unroll
            for (int c = 0; c < 64; c += 4) {
                float4 kv = *(const float4*)(kr + c);   // broadcast across warp
                s += q[c + 0] * kv.x;
                s += q[c + 1] * kv.y;
                s += q[c + 2] * kv.z;
                s += q[c + 3] * kv.w;
            }
            s *= 0.125f;   // 1/sqrt(64)

            float mn = fmaxf(m, s);
            float p  = __expf(s - mn);
            if (mn > m) {
                float corr = __expf(m - mn);   // 0 on first valid key (m=-inf)
                l *= corr;
#pragma unroll
                for (int c = 0; c < 64; c++) acc[c] *= corr;
                m = mn;
            }
            l += p;

            const float* vr = &Vs[j * 64];
#pragma unroll
            for (int c = 0; c < 64; c += 4) {
                float4 vv = *(const float4*)(vr + c);   // broadcast
                acc[c + 0] += p * vv.x;
                acc[c + 1] += p * vv.y;
                acc[c + 2] += p * vv.z;
                acc[c + 3] += p * vv.w;
            }
        }
    }

    const float inv = 1.0f / l;
    float4* op = (float4*)(out + ((size_t)b * T_ + qi) * H_);
#pragma unroll
    for (int c4 = 0; c4 < 16; c4++) {
        float4 o;
        o.x = acc[c4 * 4 + 0] * inv;
        o.y = acc[c4 * 4 + 1] * inv;
        o.z = acc[c4 * 4 + 2] * inv;
        o.w = acc[c4 * 4 + 3] * inv;
        op[c4] = o;
    }
}

// ---------------------------------------------------------------------------
extern "C" void kernel_launch(void* const* d_in, const int* in_sizes, int n_in,
                              void* d_out, int out_size)
{
    const float* x  = (const float*)d_in[0];
    const float* wq = (const float*)d_in[1];
    const float* wk = (const float*)d_in[2];
    const float* wv = (const float*)d_in[3];
    float* out = (float*)d_out;

    dim3 pgrid(M_ / 64, 3);
    proj_kernel<<<pgrid, 128>>>(x, wq, wk, wv);

    dim3 agrid(T_ / 128, B_);
    attn_kernel<<<agrid, 128>>>(out);
}

// round 4
// speedup vs baseline: 2.2652x; 2.2652x over previous
#include <cuda_runtime.h>
#include <math.h>

#define B_ 16
#define T_ 2048
#define C_ 1024
#define H_ 64
#define M_ (B_ * T_)   // 32768

typedef unsigned long long u64;

// ---- scratch (static device arrays; no allocations) ----
__device__ float g_q[(size_t)M_ * H_];
__device__ float g_k[(size_t)M_ * H_];
__device__ float g_v[(size_t)M_ * H_];

// split-K partials: 72 chunk-slots per batch (sum over 16 q-tiles of ceil((qt+1)/2))
#define NCHUNK_TOT 72
#define NSLOT (B_ * NCHUNK_TOT)          // 1152
__device__ float part_o[(size_t)NSLOT * 128 * H_];   // unnormalized acc
__device__ float part_m[NSLOT * 128];
__device__ float part_l[NSLOT * 128];

// slot s (0..71) -> (qt, ci); base[qt] = first slot of q-tile qt
__constant__ int c_qt[NCHUNK_TOT] = {
    0, 1, 2,2, 3,3, 4,4,4, 5,5,5, 6,6,6,6, 7,7,7,7,
    8,8,8,8,8, 9,9,9,9,9, 10,10,10,10,10,10, 11,11,11,11,11,11,
    12,12,12,12,12,12,12, 13,13,13,13,13,13,13,
    14,14,14,14,14,14,14,14, 15,15,15,15,15,15,15,15 };
__constant__ int c_ci[NCHUNK_TOT] = {
    0, 0, 0,1, 0,1, 0,1,2, 0,1,2, 0,1,2,3, 0,1,2,3,
    0,1,2,3,4, 0,1,2,3,4, 0,1,2,3,4,5, 0,1,2,3,4,5,
    0,1,2,3,4,5,6, 0,1,2,3,4,5,6,
    0,1,2,3,4,5,6,7, 0,1,2,3,4,5,6,7 };
__constant__ int c_base[16] = {0,1,2,4,6,9,12,16,20,25,30,36,42,49,56,64};

// ---- packed f32x2 helpers (SASS FFMA2 path, PTX-only) ----
__device__ __forceinline__ u64 pk2(float x, float y) {
    u64 r; asm("mov.b64 %0,{%1,%2};" : "=l"(r) : "f"(x), "f"(y)); return r;
}
__device__ __forceinline__ void upk2(u64 v, float& x, float& y) {
    asm("mov.b64 {%0,%1},%2;" : "=f"(x), "=f"(y) : "l"(v));
}
__device__ __forceinline__ void fma2(u64& d, u64 a, u64 b) {
    asm("fma.rn.f32x2 %0,%1,%2,%0;" : "+l"(d) : "l"(a), "l"(b));
}
__device__ __forceinline__ u64 mul2(u64 a, u64 b) {
    u64 d; asm("mul.rn.f32x2 %0,%1,%2;" : "=l"(d) : "l"(a), "l"(b)); return d;
}

// ---------------------------------------------------------------------------
// Projection GEMM with FFMA2: O[m,h] = sum_c x[m,c]*W[c,h]
// BM=64, BN=64, BK=32, 128 threads, per-thread 4 rows x 4 col-pairs.
// ---------------------------------------------------------------------------
__global__ __launch_bounds__(128) void proj_kernel(
    const float* __restrict__ x,
    const float* __restrict__ wq,
    const float* __restrict__ wk,
    const float* __restrict__ wv)
{
    const float* W;
    float* O;
    if (blockIdx.y == 0)      { W = wq; O = g_q; }
    else if (blockIdx.y == 1) { W = wk; O = g_k; }
    else                      { W = wv; O = g_v; }

    __shared__ __align__(16) float xs[64][33];
    __shared__ __align__(16) float ws[32][64];

    const int tid = threadIdx.x;
    const int ty  = tid >> 3;      // 0..15 -> rows ty*4..+3
    const int tx  = tid & 7;       // 0..7  -> cols tx*8..+7 (4 pairs)
    const int m0  = blockIdx.x * 64;

    u64 acc2[4][4];
#pragma unroll
    for (int i = 0; i < 4; i++)
#pragma unroll
        for (int p = 0; p < 4; p++) acc2[i][p] = 0ull;

    for (int k0 = 0; k0 < C_; k0 += 32) {
#pragma unroll
        for (int q = 0; q < 4; q++) {
            int i  = tid + 128 * q;
            int r  = i >> 3;
            int kq = i & 7;
            float4 v = *(const float4*)(x + (size_t)(m0 + r) * C_ + k0 + kq * 4);
            xs[r][kq * 4 + 0] = v.x;
            xs[r][kq * 4 + 1] = v.y;
            xs[r][kq * 4 + 2] = v.z;
            xs[r][kq * 4 + 3] = v.w;
        }
#pragma unroll
        for (int q = 0; q < 4; q++) {
            int i  = tid + 128 * q;
            int kr = i >> 4;
            int cq = i & 15;
            *(float4*)(&ws[kr][cq * 4]) =
                *(const float4*)(W + (size_t)(k0 + kr) * H_ + cq * 4);
        }
        __syncthreads();

#pragma unroll
        for (int kk = 0; kk < 32; kk++) {
            u64 b0 = *(const u64*)(&ws[kk][tx * 8 + 0]);
            u64 b1 = *(const u64*)(&ws[kk][tx * 8 + 2]);
            u64 b2 = *(const u64*)(&ws[kk][tx * 8 + 4]);
            u64 b3 = *(const u64*)(&ws[kk][tx * 8 + 6]);
#pragma unroll
            for (int i = 0; i < 4; i++) {
                float a = xs[ty * 4 + i][kk];
                u64 ar = pk2(a, a);
                fma2(acc2[i][0], ar, b0);
                fma2(acc2[i][1], ar, b1);
                fma2(acc2[i][2], ar, b2);
                fma2(acc2[i][3], ar, b3);
            }
        }
        __syncthreads();
    }

#pragma unroll
    for (int i = 0; i < 4; i++) {
        float o[8];
#pragma unroll
        for (int p = 0; p < 4; p++) upk2(acc2[i][p], o[2 * p], o[2 * p + 1]);
        size_t row = (size_t)(m0 + ty * 4 + i);
        *(float4*)(O + row * H_ + tx * 8)     = make_float4(o[0], o[1], o[2], o[3]);
        *(float4*)(O + row * H_ + tx * 8 + 4) = make_float4(o[4], o[5], o[6], o[7]);
    }
}

// ---------------------------------------------------------------------------
// Split-K flash attention chunk: one CTA = 128 query rows x <=256 keys.
// grid = (72, 16), block = 128. Writes unnormalized (acc, m, l).
// ---------------------------------------------------------------------------
__global__ __launch_bounds__(128) void attn_chunk_kernel()
{
    const int s   = blockIdx.x;          // chunk slot 0..71 (= base[qt]+ci)
    const int b   = blockIdx.y;
    const int qt  = c_qt[s];
    const int ci  = c_ci[s];
    const int q0  = qt * 128;
    const int tid = threadIdx.x;
    const int qi  = q0 + tid;

    const int k_begin = ci * 256;
    const int k_end   = min(k_begin + 256, q0 + 128);

    __shared__ __align__(16) float Ks[64 * 64];
    __shared__ __align__(16) float Vs[64 * 64];

    // load + pack query row
    u64 q2[32];
    {
        const float4* qp = (const float4*)(g_q + ((size_t)b * T_ + qi) * H_);
#pragma unroll
        for (int c4 = 0; c4 < 16; c4++) {
            float4 v = qp[c4];
            q2[c4 * 2 + 0] = pk2(v.x, v.y);
            q2[c4 * 2 + 1] = pk2(v.z, v.w);
        }
    }

    u64 a2[32];
#pragma unroll
    for (int c = 0; c < 32; c++) a2[c] = 0ull;
    float m = -INFINITY;
    float l = 0.0f;

    for (int kb = k_begin; kb < k_end; kb += 64) {
        __syncthreads();
        {
            const float4* Kp = (const float4*)(g_k + ((size_t)b * T_ + kb) * H_);
            const float4* Vp = (const float4*)(g_v + ((size_t)b * T_ + kb) * H_);
            float4* Ks4 = (float4*)Ks;
            float4* Vs4 = (float4*)Vs;
#pragma unroll
            for (int q8 = 0; q8 < 8; q8++) {
                int i = tid + 128 * q8;
                Ks4[i] = Kp[i];
                Vs4[i] = Vp[i];
            }
        }
        __syncthreads();

        const int jmax = min(63, qi - kb);   // causal bound (negative -> skip)

        for (int j = 0; j <= jmax; j++) {
            const float* kr = &Ks[j * 64];
            // 4 independent packed accumulators -> short dependency chain
            u64 sp0 = 0ull, sp1 = 0ull, sp2 = 0ull, sp3 = 0ull;
#pragma unroll
            for (int c = 0; c < 32; c += 4) {
                fma2(sp0, q2[c + 0], *(const u64*)(kr + 2 * c + 0));
                fma2(sp1, q2[c + 1], *(const u64*)(kr + 2 * c + 2));
                fma2(sp2, q2[c + 2], *(const u64*)(kr + 2 * c + 4));
                fma2(sp3, q2[c + 3], *(const u64*)(kr + 2 * c + 6));
            }
            float x0, x1, y0, y1, z0, z1, w0, w1;
            upk2(sp0, x0, x1); upk2(sp1, y0, y1);
            upk2(sp2, z0, z1); upk2(sp3, w0, w1);
            float sc = ((x0 + x1) + (y0 + y1)) + ((z0 + z1) + (w0 + w1));
            sc *= 0.125f;   // 1/sqrt(64)

            float mn = fmaxf(m, sc);
            float p  = __expf(sc - mn);
            if (mn > m) {                       // lazy rescale (rare)
                float corr = __expf(m - mn);    // 0 on first key (m=-inf)
                l *= corr;
                u64 cp = pk2(corr, corr);
#pragma unroll
                for (int c = 0; c < 32; c++) a2[c] = mul2(a2[c], cp);
                m = mn;
            }
            l += p;

            const float* vr = &Vs[j * 64];
            u64 pp = pk2(p, p);
#pragma unroll
            for (int c = 0; c < 32; c++)
                fma2(a2[c], pp, *(const u64*)(vr + 2 * c));
        }
    }

    // write partials (unnormalized)
    const int slot = b * NCHUNK_TOT + s;
    part_m[slot * 128 + tid] = m;
    part_l[slot * 128 + tid] = l;
    float* po = part_o + ((size_t)slot * 128 + tid) * H_;
#pragma unroll
    for (int c = 0; c < 32; c += 2) {
        float e0, e1, e2, e3;
        upk2(a2[c], e0, e1);
        upk2(a2[c + 1], e2, e3);
        *(float4*)(po + 2 * c) = make_float4(e0, e1, e2, e3);
    }
}

// ---------------------------------------------------------------------------
// Combine: merge split-K partials, normalize. grid=(16 qtiles,16 batch), block=128.
// ---------------------------------------------------------------------------
__global__ __launch_bounds__(128) void attn_combine_kernel(float* __restrict__ out)
{
    const int qt  = blockIdx.x;
    const int b   = blockIdx.y;
    const int tid = threadIdx.x;
    const int qi  = qt * 128 + tid;

    const int nch  = (qt + 2) / 2;          // ceil((qt+1)/2)
    const int base = c_base[qt];

    float mx = -INFINITY;
    float mcs[8];
#pragma unroll 8
    for (int ci = 0; ci < nch; ci++) {
        float mc = part_m[(b * NCHUNK_TOT + base + ci) * 128 + tid];
        mcs[ci] = mc;
        mx = fmaxf(mx, mc);
    }

    float L = 0.0f;
    float acc[64];
#pragma unroll
    for (int c = 0; c < 64; c++) acc[c] = 0.0f;

#pragma unroll 8
    for (int ci = 0; ci < nch; ci++) {
        const int slot = b * NCHUNK_TOT + base + ci;
        float w = __expf(mcs[ci] - mx);
        L += part_l[slot * 128 + tid] * w;
        const float4* po = (const float4*)(part_o + ((size_t)slot * 128 + tid) * H_);
#pragma unroll
        for (int c4 = 0; c4 < 16; c4++) {
            float4 v = po[c4];
            acc[c4 * 4 + 0] += w * v.x;
            acc[c4 * 4 + 1] += w * v.y;
            acc[c4 * 4 + 2] += w * v.z;
            acc[c4 * 4 + 3] += w * v.w;
        }
    }

    const float inv = 1.0f / L;
    float4* op = (float4*)(out + ((size_t)b * T_ + qi) * H_);
#pragma unroll
    for (int c4 = 0; c4 < 16; c4++)
        op[c4] = make_float4(acc[c4 * 4 + 0] * inv, acc[c4 * 4 + 1] * inv,
                             acc[c4 * 4 + 2] * inv, acc[c4 * 4 + 3] * inv);
}

// ---------------------------------------------------------------------------
extern "C" void kernel_launch(void* const* d_in, const int* in_sizes, int n_in,
                              void* d_out, int out_size)
{
    const float* x  = (const float*)d_in[0];
    const float* wq = (const float*)d_in[1];
    const float* wk = (const float*)d_in[2];
    const float* wv = (const float*)d_in[3];
    float* out = (float*)d_out;

    dim3 pgrid(M_ / 64, 3);
    proj_kernel<<<pgrid, 128>>>(x, wq, wk, wv);

    dim3 cgrid(NCHUNK_TOT, B_);
    attn_chunk_kernel<<<cgrid, 128>>>();

    dim3 ggrid(T_ / 128, B_);
    attn_combine_kernel<<<ggrid, 128>>>(out);
}

// round 5
// speedup vs baseline: 5.7191x; 2.5248x over previous
#include <cuda_runtime.h>
#include <cuda_bf16.h>
#include <math.h>

#define B_ 16
#define T_ 2048
#define C_ 1024
#define H_ 64
#define M_ (B_ * T_)   // 32768

typedef unsigned int u32;
typedef unsigned short u16;

// ---------------- static device scratch (no allocations) ----------------
// Q, K row-major [m][64] as packed bf16-pairs (u32), hi and lo planes.
__device__ u32 g_qh[(size_t)M_ * 32], g_ql[(size_t)M_ * 32];
__device__ u32 g_kh[(size_t)M_ * 32], g_kl[(size_t)M_ * 32];
// V transposed per batch: [b][h=64][t=2048] bf16 -> u32 pairs along t.
__device__ u32 g_vth[(size_t)B_ * 64 * 1024], g_vtl[(size_t)B_ * 64 * 1024];
// W transposed: [w=3][n=64][k=1024] bf16 -> u32 pairs along k.
__device__ u32 g_wth[3 * 64 * 512], g_wtl[3 * 64 * 512];

// split-K partials: q-tiles of 64 rows, chunks of <=256 keys.
#define NQT 32
#define NCH_TOT 144                 // sum over qt of (qt/4 + 1)
#define NSLOT (B_ * NCH_TOT)        // 2304
__device__ float part_o[(size_t)NSLOT * 64 * H_];   // ~37.7 MB
__device__ float part_m[NSLOT * 64];
__device__ float part_l[NSLOT * 64];

__constant__ int c_base[NQT + 1] = {
    0,1,2,3, 4,6,8,10, 12,15,18,21, 24,28,32,36,
    40,45,50,55, 60,66,72,78, 84,91,98,105, 112,120,128,136, 144 };

// ---------------- helpers ----------------
__device__ __forceinline__ void split1(float x, u16& h, u16& l) {
    __nv_bfloat16 bh = __float2bfloat16_rn(x);
    float r = x - __bfloat162float(bh);
    __nv_bfloat16 bl = __float2bfloat16_rn(r);
    h = __bfloat16_as_ushort(bh);
    l = __bfloat16_as_ushort(bl);
}
// pack (a,b) -> bf16x2 u32 (a in low half = smaller k index), hi & lo planes
__device__ __forceinline__ void split2(float a, float b, u32& hi, u32& lo) {
    u16 ha, la, hb, lb;
    split1(a, ha, la);
    split1(b, hb, lb);
    hi = (u32)ha | ((u32)hb << 16);
    lo = (u32)la | ((u32)lb << 16);
}

// m16n8k16 bf16 MMA, fp32 accumulate (D += A*B)
__device__ __forceinline__ void mma_bf16(float* c,
    u32 a0, u32 a1, u32 a2, u32 a3, u32 b0, u32 b1) {
    asm volatile(
        "mma.sync.aligned.m16n8k16.row.col.f32.bf16.bf16.f32 "
        "{%0,%1,%2,%3},{%4,%5,%6,%7},{%8,%9},{%0,%1,%2,%3};"
        : "+f"(c[0]), "+f"(c[1]), "+f"(c[2]), "+f"(c[3])
        : "r"(a0), "r"(a1), "r"(a2), "r"(a3), "r"(b0), "r"(b1));
}

// ---------------------------------------------------------------------------
// W pre-convert: W[c][h] f32 -> g_wt[w][n=h][k-pair] bf16 hi/lo (transposed)
// ---------------------------------------------------------------------------
__global__ void wconv_kernel(const float* __restrict__ wq,
                             const float* __restrict__ wk,
                             const float* __restrict__ wv) {
    int idx = blockIdx.x * 256 + threadIdx.x;      // one u32 pair per thread
    if (idx >= 3 * 64 * 512) return;
    int w   = idx / (64 * 512);
    int rem = idx % (64 * 512);
    int n   = rem / 512;
    int kp  = rem % 512;
    const float* W = (w == 0) ? wq : (w == 1 ? wk : wv);
    float a = W[(size_t)(2 * kp) * 64 + n];
    float b = W[(size_t)(2 * kp + 1) * 64 + n];
    u32 hi, lo;
    split2(a, b, hi, lo);
    g_wth[idx] = hi;
    g_wtl[idx] = lo;
}

// ---------------------------------------------------------------------------
// Projection GEMM (split-bf16 MMA): O[m,h] = sum_c X[m,c] * W[c,h]
// grid = (3 sel, 512 m-tiles), block = 128 (4 warps x m16). BK = 32.
// sel 0 -> Q (pre-scaled by 0.125, row-major hi/lo)
// sel 1 -> K (row-major hi/lo)
// sel 2 -> V (transposed hi/lo)
// ---------------------------------------------------------------------------
__global__ __launch_bounds__(128) void proj_kernel(const float* __restrict__ x)
{
    __shared__ u32 xh[64 * 20], xl[64 * 20];   // X tile [row][k-pair], stride 20
    __shared__ u32 wh[64 * 20], wl[64 * 20];   // Wt tile [n][k-pair], stride 20

    const int tid  = threadIdx.x;
    const int w    = tid >> 5;
    const int lane = tid & 31;
    const int g    = lane >> 2;
    const int tig  = lane & 3;
    const int sel  = blockIdx.x;
    const int m0   = blockIdx.y * 64;

    const u32* wtH = g_wth + sel * 64 * 512;
    const u32* wtL = g_wtl + sel * 64 * 512;

    float acc[8][4];
#pragma unroll
    for (int nt = 0; nt < 8; nt++)
#pragma unroll
        for (int i = 0; i < 4; i++) acc[nt][i] = 0.0f;

    for (int k0 = 0; k0 < C_; k0 += 32) {
        __syncthreads();
        // stage X 64x32 f32 -> hi/lo pairs
#pragma unroll
        for (int q = 0; q < 4; q++) {
            int i  = tid + 128 * q;
            int r  = i >> 3;
            int kq = i & 7;
            float4 v = *(const float4*)(x + (size_t)(m0 + r) * C_ + k0 + kq * 4);
            u32 h0, l0, h1, l1;
            split2(v.x, v.y, h0, l0);
            split2(v.z, v.w, h1, l1);
            xh[r * 20 + kq * 2]     = h0;
            xh[r * 20 + kq * 2 + 1] = h1;
            xl[r * 20 + kq * 2]     = l0;
            xl[r * 20 + kq * 2 + 1] = l1;
        }
        // stage Wt tile (pre-converted)
#pragma unroll
        for (int q = 0; q < 8; q++) {
            int i = tid + 128 * q;
            int n = i >> 4;
            int c = i & 15;
            wh[n * 20 + c] = wtH[n * 512 + (k0 >> 1) + c];
            wl[n * 20 + c] = wtL[n * 512 + (k0 >> 1) + c];
        }
        __syncthreads();

        const int rg  = (16 * w + g) * 20;
        const int rg8 = rg + 160;
#pragma unroll
        for (int ks = 0; ks < 2; ks++) {
            int c0 = 8 * ks + tig;
            u32 ah0 = xh[rg + c0], ah1 = xh[rg8 + c0];
            u32 ah2 = xh[rg + c0 + 4], ah3 = xh[rg8 + c0 + 4];
            u32 al0 = xl[rg + c0], al1 = xl[rg8 + c0];
            u32 al2 = xl[rg + c0 + 4], al3 = xl[rg8 + c0 + 4];
#pragma unroll
            for (int nt = 0; nt < 8; nt++) {
                int br = (8 * nt + g) * 20 + c0;
                u32 bh0 = wh[br], bh1 = wh[br + 4];
                u32 bl0 = wl[br], bl1 = wl[br + 4];
                mma_bf16(acc[nt], ah0, ah1, ah2, ah3, bh0, bh1);
                mma_bf16(acc[nt], ah0, ah1, ah2, ah3, bl0, bl1);
                mma_bf16(acc[nt], al0, al1, al2, al3, bh0, bh1);
            }
        }
    }

    // epilogue
    const int mg = m0 + 16 * w + g;       // rows mg (c0,c1) and mg+8 (c2,c3)
    if (sel < 2) {
        u32* H = sel ? g_kh : g_qh;
        u32* L = sel ? g_kl : g_ql;
        const float sc = sel ? 1.0f : 0.125f;   // fold 1/sqrt(64) into Q
#pragma unroll
        for (int nt = 0; nt < 8; nt++) {
            u32 hi, lo;
            split2(sc * acc[nt][0], sc * acc[nt][1], hi, lo);
            H[(size_t)mg * 32 + 4 * nt + tig] = hi;
            L[(size_t)mg * 32 + 4 * nt + tig] = lo;
            split2(sc * acc[nt][2], sc * acc[nt][3], hi, lo);
            H[(size_t)(mg + 8) * 32 + 4 * nt + tig] = hi;
            L[(size_t)(mg + 8) * 32 + 4 * nt + tig] = lo;
        }
    } else {
        u16* VH = (u16*)g_vth;
        u16* VL = (u16*)g_vtl;
        const int b = mg >> 11;
        const int t = mg & 2047;
#pragma unroll
        for (int nt = 0; nt < 8; nt++) {
            int h0 = 8 * nt + 2 * tig;
            u16 hh, ll;
            split1(acc[nt][0], hh, ll);
            VH[((size_t)(b * 64 + h0)) * 2048 + t] = hh;
            VL[((size_t)(b * 64 + h0)) * 2048 + t] = ll;
            split1(acc[nt][1], hh, ll);
            VH[((size_t)(b * 64 + h0 + 1)) * 2048 + t] = hh;
            VL[((size_t)(b * 64 + h0 + 1)) * 2048 + t] = ll;
            split1(acc[nt][2], hh, ll);
            VH[((size_t)(b * 64 + h0)) * 2048 + t + 8] = hh;
            VL[((size_t)(b * 64 + h0)) * 2048 + t + 8] = ll;
            split1(acc[nt][3], hh, ll);
            VH[((size_t)(b * 64 + h0 + 1)) * 2048 + t + 8] = hh;
            VL[((size_t)(b * 64 + h0 + 1)) * 2048 + t + 8] = ll;
        }
    }
}

// ---------------------------------------------------------------------------
// Split-K flash-attention chunk (MMA): CTA = 64 q-rows x <=256 keys.
// grid = (144, 16), block = 128 (4 warps x m16).
// ---------------------------------------------------------------------------
__global__ __launch_bounds__(128) void attn_chunk_kernel()
{
    __shared__ u32 Kh[64 * 36], Kl[64 * 36];   // [key][h-pair], stride 36
    __shared__ u32 Vh[64 * 36], Vl[64 * 36];   // [h][key-pair], stride 36

    const int s = blockIdx.x;
    const int b = blockIdx.y;
    int qt = 0;
    while (c_base[qt + 1] <= s) qt++;
    const int ci = s - c_base[qt];
    const int q0 = qt * 64;

    const int tid  = threadIdx.x;
    const int w    = tid >> 5;
    const int lane = tid & 31;
    const int g    = lane >> 2;
    const int tig  = lane & 3;

    const int kbeg = ci * 256;
    const int kend = min(kbeg + 256, q0 + 64);

    // resident Q fragments (hi/lo), 4 k-steps
    u32 qfh[4][4], qfl[4][4];
    {
        const size_t qrow  = ((size_t)b * T_ + q0 + 16 * w + g) * 32;
        const size_t qrow8 = qrow + 8 * 32;
#pragma unroll
        for (int ks = 0; ks < 4; ks++) {
            qfh[ks][0] = g_qh[qrow  + 8 * ks + tig];
            qfh[ks][1] = g_qh[qrow8 + 8 * ks + tig];
            qfh[ks][2] = g_qh[qrow  + 8 * ks + tig + 4];
            qfh[ks][3] = g_qh[qrow8 + 8 * ks + tig + 4];
            qfl[ks][0] = g_ql[qrow  + 8 * ks + tig];
            qfl[ks][1] = g_ql[qrow8 + 8 * ks + tig];
            qfl[ks][2] = g_ql[qrow  + 8 * ks + tig + 4];
            qfl[ks][3] = g_ql[qrow8 + 8 * ks + tig + 4];
        }
    }

    float o[8][4];
#pragma unroll
    for (int ht = 0; ht < 8; ht++)
#pragma unroll
        for (int i = 0; i < 4; i++) o[ht][i] = 0.0f;
    float m0r = -INFINITY, m1r = -INFINITY, l0 = 0.0f, l1 = 0.0f;

    for (int kb = kbeg; kb < kend; kb += 64) {
        __syncthreads();
        {
            const u32* KH = g_kh + ((size_t)b * T_ + kb) * 32;
            const u32* KL = g_kl + ((size_t)b * T_ + kb) * 32;
            const u32* VH = g_vth + (size_t)b * 64 * 1024 + (kb >> 1);
            const u32* VL = g_vtl + (size_t)b * 64 * 1024 + (kb >> 1);
#pragma unroll
            for (int q = 0; q < 16; q++) {
                int i = tid + 128 * q;
                int r = i >> 5;
                int c = i & 31;
                Kh[r * 36 + c] = KH[(size_t)r * 32 + c];
                Kl[r * 36 + c] = KL[(size_t)r * 32 + c];
                Vh[r * 36 + c] = VH[(size_t)r * 1024 + c];
                Vl[r * 36 + c] = VL[(size_t)r * 1024 + c];
            }
        }
        __syncthreads();

        // ---- S = Q K^T (scale pre-folded into Q) ----
        float sA[8][4];
#pragma unroll
        for (int nt = 0; nt < 8; nt++)
#pragma unroll
            for (int i = 0; i < 4; i++) sA[nt][i] = 0.0f;
#pragma unroll
        for (int ks = 0; ks < 4; ks++) {
#pragma unroll
            for (int nt = 0; nt < 8; nt++) {
                int br = (8 * nt + g) * 36 + 8 * ks + tig;
                u32 bh0 = Kh[br], bh1 = Kh[br + 4];
                u32 bl0 = Kl[br], bl1 = Kl[br + 4];
                mma_bf16(sA[nt], qfh[ks][0], qfh[ks][1], qfh[ks][2], qfh[ks][3], bh0, bh1);
                mma_bf16(sA[nt], qfh[ks][0], qfh[ks][1], qfh[ks][2], qfh[ks][3], bl0, bl1);
                mma_bf16(sA[nt], qfl[ks][0], qfl[ks][1], qfl[ks][2], qfl[ks][3], bh0, bh1);
            }
        }

        // ---- causal mask (only diagonal block kb == q0) ----
        if (kb == q0) {
            const int r0 = 16 * w + g, r1 = r0 + 8;
#pragma unroll
            for (int nt = 0; nt < 8; nt++) {
                int n0 = 8 * nt + 2 * tig;
                if (n0     > r0) sA[nt][0] = -1e30f;
                if (n0 + 1 > r0) sA[nt][1] = -1e30f;
                if (n0     > r1) sA[nt][2] = -1e30f;
                if (n0 + 1 > r1) sA[nt][3] = -1e30f;
            }
        }

        // ---- online softmax (rows r0 = c0/c1, r1 = c2/c3) ----
        float rx0 = -INFINITY, rx1 = -INFINITY;
#pragma unroll
        for (int nt = 0; nt < 8; nt++) {
            rx0 = fmaxf(rx0, fmaxf(sA[nt][0], sA[nt][1]));
            rx1 = fmaxf(rx1, fmaxf(sA[nt][2], sA[nt][3]));
        }
        rx0 = fmaxf(rx0, __shfl_xor_sync(0xffffffffu, rx0, 1));
        rx0 = fmaxf(rx0, __shfl_xor_sync(0xffffffffu, rx0, 2));
        rx1 = fmaxf(rx1, __shfl_xor_sync(0xffffffffu, rx1, 1));
        rx1 = fmaxf(rx1, __shfl_xor_sync(0xffffffffu, rx1, 2));

        float mn0 = fmaxf(m0r, rx0), mn1 = fmaxf(m1r, rx1);
        float cor0 = __expf(m0r - mn0), cor1 = __expf(m1r - mn1);
        m0r = mn0; m1r = mn1;

        float ps0 = 0.0f, ps1 = 0.0f;
#pragma unroll
        for (int nt = 0; nt < 8; nt++) {
            sA[nt][0] = __expf(sA[nt][0] - mn0);
            sA[nt][1] = __expf(sA[nt][1] - mn0);
            sA[nt][2] = __expf(sA[nt][2] - mn1);
            sA[nt][3] = __expf(sA[nt][3] - mn1);
            ps0 += sA[nt][0] + sA[nt][1];
            ps1 += sA[nt][2] + sA[nt][3];
        }
        ps0 += __shfl_xor_sync(0xffffffffu, ps0, 1);
        ps0 += __shfl_xor_sync(0xffffffffu, ps0, 2);
        ps1 += __shfl_xor_sync(0xffffffffu, ps1, 1);
        ps1 += __shfl_xor_sync(0xffffffffu, ps1, 2);
        l0 = l0 * cor0 + ps0;
        l1 = l1 * cor1 + ps1;
#pragma unroll
        for (int ht = 0; ht < 8; ht++) {
            o[ht][0] *= cor0; o[ht][1] *= cor0;
            o[ht][2] *= cor1; o[ht][3] *= cor1;
        }

        // ---- O += P V (P from S fragments, split hi/lo) ----
#pragma unroll
        for (int kk = 0; kk < 4; kk++) {
            u32 ph[4], pl[4];
            split2(sA[2 * kk][0],     sA[2 * kk][1],     ph[0], pl[0]);
            split2(sA[2 * kk][2],     sA[2 * kk][3],     ph[1], pl[1]);
            split2(sA[2 * kk + 1][0], sA[2 * kk + 1][1], ph[2], pl[2]);
            split2(sA[2 * kk + 1][2], sA[2 * kk + 1][3], ph[3], pl[3]);
#pragma unroll
            for (int ht = 0; ht < 8; ht++) {
                int br = (8 * ht + g) * 36 + 8 * kk + tig;
                u32 vh0 = Vh[br], vh1 = Vh[br + 4];
                u32 vl0 = Vl[br], vl1 = Vl[br + 4];
                mma_bf16(o[ht], ph[0], ph[1], ph[2], ph[3], vh0, vh1);
                mma_bf16(o[ht], ph[0], ph[1], ph[2], ph[3], vl0, vl1);
                mma_bf16(o[ht], pl[0], pl[1], pl[2], pl[3], vh0, vh1);
            }
        }
    }

    // ---- write partials ----
    const int slot = b * NCH_TOT + s;
    const int r0 = 16 * w + g;
    if (tig == 0) {
        part_m[slot * 64 + r0]     = m0r;
        part_m[slot * 64 + r0 + 8] = m1r;
        part_l[slot * 64 + r0]     = l0;
        part_l[slot * 64 + r0 + 8] = l1;
    }
    float* po = part_o + (size_t)slot * 64 * H_;
#pragma unroll
    for (int ht = 0; ht < 8; ht++) {
        int col = 8 * ht + 2 * tig;
        *(float2*)(po + (size_t)r0 * H_ + col)       = make_float2(o[ht][0], o[ht][1]);
        *(float2*)(po + (size_t)(r0 + 8) * H_ + col) = make_float2(o[ht][2], o[ht][3]);
    }
}

// ---------------------------------------------------------------------------
// Combine: merge chunk partials, normalize. grid = (16, 16), block = 128.
// ---------------------------------------------------------------------------
__global__ __launch_bounds__(128) void combine_kernel(float* __restrict__ out)
{
    const int b   = blockIdx.y;
    const int row = blockIdx.x * 128 + threadIdx.x;   // 0..2047
    const int qt  = row >> 6;
    const int rr  = row & 63;
    const int nch  = qt / 4 + 1;
    const int base = c_base[qt];

    float mx = -INFINITY;
    for (int ci = 0; ci < nch; ci++)
        mx = fmaxf(mx, part_m[(b * NCH_TOT + base + ci) * 64 + rr]);

    float L = 0.0f;
    float acc[64];
#pragma unroll
    for (int c = 0; c < 64; c++) acc[c] = 0.0f;

    for (int ci = 0; ci < nch; ci++) {
        const int slot = b * NCH_TOT + base + ci;
        float wgt = __expf(part_m[slot * 64 + rr] - mx);
        L += part_l[slot * 64 + rr] * wgt;
        const float4* po = (const float4*)(part_o + ((size_t)slot * 64 + rr) * H_);
#pragma unroll
        for (int c4 = 0; c4 < 16; c4++) {
            float4 v = po[c4];
            acc[c4 * 4 + 0] += wgt * v.x;
            acc[c4 * 4 + 1] += wgt * v.y;
            acc[c4 * 4 + 2] += wgt * v.z;
            acc[c4 * 4 + 3] += wgt * v.w;
        }
    }

    const float inv = 1.0f / L;
    float4* op = (float4*)(out + ((size_t)b * T_ + row) * H_);
#pragma unroll
    for (int c4 = 0; c4 < 16; c4++)
        op[c4] = make_float4(acc[c4 * 4 + 0] * inv, acc[c4 * 4 + 1] * inv,
                             acc[c4 * 4 + 2] * inv, acc[c4 * 4 + 3] * inv);
}

// ---------------------------------------------------------------------------
extern "C" void kernel_launch(void* const* d_in, const int* in_sizes, int n_in,
                              void* d_out, int out_size)
{
    const float* x  = (const float*)d_in[0];
    const float* wq = (const float*)d_in[1];
    const float* wk = (const float*)d_in[2];
    const float* wv = (const float*)d_in[3];
    float* out = (float*)d_out;

    wconv_kernel<<<384, 256>>>(wq, wk, wv);

    dim3 pgrid(3, M_ / 64);
    proj_kernel<<<pgrid, 128>>>(x);

    dim3 cgrid(NCH_TOT, B_);
    attn_chunk_kernel<<<cgrid, 128>>>();

    dim3 ggrid(T_ / 128, B_);
    combine_kernel<<<ggrid, 128>>>(out);
}